// round 16
// baseline (speedup 1.0000x reference)
#include <cuda_runtime.h>

#define N_PTS   8192
#define C_DIM   64
#define C4      (C_DIM/4)
#define NQ      (3*N_PTS)                 // 24576 queries
#define VOFF    ((size_t)4*N_PTS*C_DIM)   // float offset of out_coords

#define G       64
#define NCELL   (G*G)                     // 4096 cells
#define HC      0.015625f                 // 1/64, exact in fp32

#define TPB      256
#define BIN_CTAS 32
#define QPC      16                       // queries per CTA (2 per warp)
#define QW_CTAS  (NQ/QPC)                 // 1536 CTAs
#define NITEM    (N_PTS*C4 + N_PTS)       // 139264 copy items
#define ITEMS    91                       // ceil(NITEM / QW_CTAS)
#define FULL     0xffffffffu

typedef unsigned long long u64;
typedef unsigned int       u32;

// Row-major-cell CSR (rebuilt every launch; g_cnt re-zeroed at k_bin exit so
// every launch/replay enters with a clean histogram).
__device__ int    g_cnt[NCELL];           // zero at entry (module init / exit)
__device__ int    g_start[NCELL + 1];
__device__ int    g_cur[NCELL];
__device__ float4 g_pts[N_PTS];           // (x, y, |c|^2, idx bits), CSR order

// Grid-barrier counters (reset each use; replay-safe).
__device__ volatile int g_arr[2];
__device__ int          g_dep[2];

__device__ __forceinline__ int clamp_cell(float v) {
    int c = (int)floorf(v * 64.0f);
    return min(max(c, 0), G - 1);
}

__device__ __forceinline__ void gbar(int b) {
    __syncthreads();
    if (threadIdx.x == 0) {
        __threadfence();
        atomicAdd((int*)&g_arr[b], 1);
        while (g_arr[b] != BIN_CTAS) __nanosleep(32);
        int p = atomicAdd(&g_dep[b], 1);
        if (p == BIN_CTAS - 1) {
            g_dep[b] = 0;
            __threadfence();
            *(int*)&g_arr[b] = 0;
        }
    }
    __syncthreads();
}

// ---------------------------------------------------------------------------
// K_bin: histogram -> barrier -> prefix scan (CTA 0) -> barrier -> CSR
// scatter + re-zero histogram for the next launch. 32 CTAs, 1 pt/thread.
// Intra-cell order nondeterministic; downstream reduction is a set-min.
// ---------------------------------------------------------------------------
__global__ void __launch_bounds__(TPB)
k_bin(const float2* __restrict__ c2)
{
    const int gi = blockIdx.x * TPB + threadIdx.x;   // 0..8191

    // phase 1: histogram (g_cnt is zero at entry by invariant)
    float2 c = __ldg(&c2[gi]);
    const int cell = clamp_cell(c.y) * G + clamp_cell(c.x);
    atomicAdd(&g_cnt[cell], 1);
    gbar(0);

    // phase 2: exclusive prefix scan over 4096 cells (CTA 0, 16 cells/thread)
    if (blockIdx.x == 0) {
        __shared__ int wsum[8];
        const int t = threadIdx.x;
        const int lane = t & 31, w = t >> 5;
        int v[16], s = 0;
        #pragma unroll
        for (int k = 0; k < 16; k++) {
            v[k] = __ldcg(&g_cnt[t * 16 + k]);
            s += v[k];
        }
        int inc = s;
        #pragma unroll
        for (int o = 1; o < 32; o <<= 1) {
            int n = __shfl_up_sync(FULL, inc, o);
            if (lane >= o) inc += n;
        }
        if (lane == 31) wsum[w] = inc;
        __syncthreads();
        if (t < 8) {
            int x = wsum[t];
            #pragma unroll
            for (int o = 1; o < 8; o <<= 1) {
                int n = __shfl_up_sync(0xffu, x, o);
                if (t >= o) x += n;
            }
            wsum[t] = x;
        }
        __syncthreads();
        int run = (inc - s) + (w ? wsum[w - 1] : 0);
        #pragma unroll
        for (int k = 0; k < 16; k++) {
            g_start[t * 16 + k] = run;
            g_cur[t * 16 + k]   = run;
            run += v[k];
        }
        if (t == 255) g_start[NCELL] = run;     // = N_PTS
    }
    gbar(1);

    // phase 3: CSR scatter + restore the zero-histogram invariant
    float sc = __fadd_rn(__fmul_rn(c.x, c.x), __fmul_rn(c.y, c.y));
    int pos = atomicAdd(&g_cur[cell], 1);
    g_pts[pos] = make_float4(c.x, c.y, sc, __int_as_float(gi));
    if (gi < NCELL) g_cnt[gi] = 0;
}

// ---------------------------------------------------------------------------
// Warp-collective exact NN. Row-major-cell CSR means a square's points in
// one y-row are ONE contiguous range [start[y*G+x0], start[y*G+x1+1]).
// Fast path: 3x3 square as 3 concatenated intervals, single warp chunk.
// Exact per-pair semantics (verified bit-identical to reference):
//   m = fma(a1, py, RN(a0*px));  d = fma(m, -2, RN(sa+sc))
// Lexicographic (ordered-d, idx) min == jnp.argmin first occurrence.
// ---------------------------------------------------------------------------
__device__ __forceinline__ int warp_nn(float a0, float a1, float sa, int lane)
{
    const float sa_ = sa;
    const int cx = clamp_cell(a0);
    const int cy = clamp_cell(a1);

    // query clearance to the point domain [0,1] per axis
    const float dxo = fmaxf(fmaxf(a0 - 1.0f, -a0), 0.0f);
    const float dyo = fmaxf(fmaxf(a1 - 1.0f, -a1), 0.0f);
    const float dxo2 = dxo * dxo;
    const float dyo2 = dyo * dyo;

    u64 bestk = ~0ull;

    #define EVAL_PT(P) do {                                                  \
        float m_ = __fmaf_rn(a1, (P).y, __fmul_rn(a0, (P).x));               \
        float d_ = __fmaf_rn(m_, -2.0f, __fadd_rn(sa_, (P).z));              \
        u32 ub_ = __float_as_uint(d_);                                       \
        ub_ = (ub_ & 0x80000000u) ? ~ub_ : (ub_ | 0x80000000u);              \
        u64 key_ = ((u64)ub_ << 32) | (u32)__float_as_uint((P).w);           \
        bestk = (key_ < bestk) ? key_ : bestk;                               \
    } while (0)

    // lb^2 to the unscanned region outside square [x0,x1]x[y0,y1]:
    // per side-slab, (axis gap)^2 + (clearance to [0,1] in other axis)^2.
    #define LB2(x0_, x1_, y0_, y1_, out_) do {                               \
        float l_ = __int_as_float(0x7f800000);                               \
        if ((x0_) > 0) {                                                     \
            float dx = fmaxf(__fsub_rn(a0, (float)(x0_) * HC), 0.0f);        \
            l_ = fminf(l_, __fmaf_rn(dx, dx, dyo2));                         \
        }                                                                    \
        if ((x1_) < G - 1) {                                                 \
            float dx = fmaxf(__fsub_rn((float)((x1_) + 1) * HC, a0), 0.0f);  \
            l_ = fminf(l_, __fmaf_rn(dx, dx, dyo2));                         \
        }                                                                    \
        if ((y0_) > 0) {                                                     \
            float dy = fmaxf(__fsub_rn(a1, (float)(y0_) * HC), 0.0f);        \
            l_ = fminf(l_, __fmaf_rn(dy, dy, dxo2));                         \
        }                                                                    \
        if ((y1_) < G - 1) {                                                 \
            float dy = fmaxf(__fsub_rn((float)((y1_) + 1) * HC, a1), 0.0f);  \
            l_ = fminf(l_, __fmaf_rn(dy, dy, dxo2));                         \
        }                                                                    \
        (out_) = l_;                                                         \
    } while (0)

    // warp-wide best-so-far distance (empty -> +inf)
    #define WARP_BD(out_) do {                                               \
        u32 mu_ = __reduce_min_sync(FULL, (u32)(bestk >> 32));               \
        if (mu_ == 0xffffffffu)      (out_) = __int_as_float(0x7f800000);    \
        else if (mu_ & 0x80000000u)  (out_) = __uint_as_float(mu_ & 0x7fffffffu); \
        else                         (out_) = __uint_as_float(~mu_);         \
    } while (0)

    // ---- fast path: r = 1 (3x3, clipped), 3 concatenated row intervals ----
    {
        const int x0 = max(cx - 1, 0), x1 = min(cx + 1, G - 1);
        const int y0 = max(cy - 1, 0), y1 = min(cy + 1, G - 1);

        int s0, e0, s1, e1, s2, e2;
        {
            int ya = cy - 1, yc = cy + 1, b1 = cy * G;
            bool va = (ya >= 0), vc = (yc <= G - 1);
            s0 = va ? __ldg(&g_start[ya * G + x0])     : 0;
            e0 = va ? __ldg(&g_start[ya * G + x1 + 1]) : 0;
            s1 = __ldg(&g_start[b1 + x0]);
            e1 = __ldg(&g_start[b1 + x1 + 1]);
            s2 = vc ? __ldg(&g_start[yc * G + x0])     : 0;
            e2 = vc ? __ldg(&g_start[yc * G + x1 + 1]) : 0;
        }
        const int l0 = e0 - s0, l1 = e1 - s1;
        const int o1 = l0, o2 = l0 + l1;
        const int tot = o2 + (e2 - s2);

        for (int t0 = 0; t0 < tot; t0 += 32) {
            const int t = t0 + lane;
            if (t < tot) {
                int idx = (t < o1) ? (s0 + t)
                        : (t < o2) ? (s1 + (t - o1))
                                   : (s2 + (t - o2));
                float4 p = __ldg(&g_pts[idx]);
                EVAL_PT(p);
            }
        }

        float lb2; LB2(x0, x1, y0, y1, lb2);
        if (lb2 > 1e18f) goto done;
        float bd;  WARP_BD(bd);
        if (lb2 > bd + 1e-4f) goto done;        // margin >> fp slack (~4e-6)
    }

    // ---- rare path: expanding squares r = 3, 7, ... (rescans min-safe) ----
    {
        int r = 3;
        while (true) {
            const int x0 = max(cx - r, 0), x1 = min(cx + r, G - 1);
            const int y0 = max(cy - r, 0), y1 = min(cy + r, G - 1);

            for (int y = y0; y <= y1; y++) {
                int s = __ldg(&g_start[y * G + x0]);
                int e = __ldg(&g_start[y * G + x1 + 1]);
                for (int t = s + lane; t < e; t += 32) {
                    float4 p = __ldg(&g_pts[t]);
                    EVAL_PT(p);
                }
            }

            float lb2; LB2(x0, x1, y0, y1, lb2);
            if (lb2 > 1e18f) break;
            float bd;  WARP_BD(bd);
            if (lb2 > bd + 1e-4f) break;
            r = 2 * r + 1;
        }
    }
done:
    #undef EVAL_PT
    #undef LB2
    #undef WARP_BD

    // final lexicographic (d, idx) warp reduction
    u32 bub = (u32)(bestk >> 32);
    u32 mu  = __reduce_min_sync(FULL, bub);
    u32 cnd = (bub == mu) ? (u32)bestk : 0xffffffffu;
    return (int)__reduce_min_sync(FULL, cnd);
}

// ---------------------------------------------------------------------------
// K_query: 16 queries per CTA (2 per warp) + distributed output copies +
// coalesced value-row gather (exactly 1 float4 per thread).
// ---------------------------------------------------------------------------
__global__ void __launch_bounds__(TPB)
k_query(const float2* __restrict__ c2,
        const float*  __restrict__ spacing,
        const float*  __restrict__ shift,
        const float4* __restrict__ val4,
        float*        __restrict__ out)
{
    __shared__ int widx[QPC];
    const int lane = threadIdx.x & 31;
    const int wid  = threadIdx.x >> 5;

    float s0  = __ldg(&spacing[0]), s1  = __ldg(&spacing[1]);
    float sh0 = __ldg(&shift[0]),   sh1 = __ldg(&shift[1]);

    // ---- distributed output copies (independent of binning results) ----
    if (threadIdx.x < ITEMS) {
        int item = blockIdx.x * ITEMS + threadIdx.x;
        if (item < N_PTS * C4) {
            reinterpret_cast<float4*>(out)[item] = __ldg(&val4[item]);
        } else if (item < NITEM) {
            int i = item - N_PTS * C4;
            float2 cc = __ldg(&c2[i]);
            float xs = __fadd_rn(cc.x, s0);
            float ys = __fadd_rn(cc.y, s1);
            float2* outc = reinterpret_cast<float2*>(out + VOFF);
            outc[i]             = cc;
            outc[N_PTS   + i]   = make_float2(xs,   ys);
            outc[2*N_PTS + i]   = make_float2(cc.x, ys);
            outc[3*N_PTS + i]   = make_float2(xs,   cc.y);
        }
    }

    // ---- 2 queries per warp, sequential ----
    #pragma unroll
    for (int k = 0; k < 2; k++) {
        const int q = blockIdx.x * QPC + wid * 2 + k;   // 0..24575
        const int g = q >> 13;
        const int i = q & (N_PTS - 1);

        float2 c = __ldg(&c2[i]);
        float nc0, nc1;
        if (g == 0)      { nc0 = __fadd_rn(c.x, s0); nc1 = __fadd_rn(c.y, s1); }
        else if (g == 1) { nc0 = c.x;                nc1 = __fadd_rn(c.y, s1); }
        else             { nc0 = __fadd_rn(c.x, s0); nc1 = c.y;                }

        const float a0 = __fsub_rn(nc0, sh0);
        const float a1 = __fsub_rn(nc1, sh1);
        const float sa = __fadd_rn(__fmul_rn(a0, a0), __fmul_rn(a1, a1));

        int win = warp_nn(a0, a1, sa, lane);
        if (lane == 0) widx[wid * 2 + k] = win;
    }
    __syncthreads();

    // ---- coalesced gather: 16 winner rows, 1 float4 per thread ----
    {
        int rr  = threadIdx.x >> 4;         // 0..15
        int ccx = threadIdx.x & (C4 - 1);   // 0..15
        int row = blockIdx.x * QPC + rr;
        reinterpret_cast<float4*>(out)[(size_t)(N_PTS + row) * C4 + ccx] =
            __ldg(&val4[(size_t)widx[rr] * C4 + ccx]);
    }
}

// ---------------------------------------------------------------------------
extern "C" void kernel_launch(void* const* d_in, const int* in_sizes, int n_in,
                              void* d_out, int out_size)
{
    const float4* val4    = (const float4*)d_in[0];
    const float2* c2      = (const float2*)d_in[1];
    const float*  spacing = (const float*) d_in[2];
    const float*  shift   = (const float*) d_in[3];
    float* out = (float*)d_out;

    k_bin<<<BIN_CTAS, TPB>>>(c2);
    k_query<<<QW_CTAS, TPB>>>(c2, spacing, shift, val4, out);
}